// round 14
// baseline (speedup 1.0000x reference)
#include <cuda_runtime.h>
#include <math.h>
#include <stdint.h>

// Problem constants
#define TB   8192   // T
#define NB   128    // batch
#define NS   512    // states
#define NM   64     // symbols
#define NCL  16     // clusters (batch groups)
#define RPC  8      // batch rows per cluster
#define CPC  8      // CTAs per cluster (state slices)
#define NC   64     // state columns per CTA
#define RSW  260    // p row stride in 32-bit words (256 data + 4 pad)
#define PBD  10     // part b-dim pad (float2 aligned, 2-way conflicts max)
#define TXQ  2176   // expected tx bytes per quarter: 2 src * (1024 p + 64 lmax)
#define NT   512    // threads

// Dynamic SMEM layout (bytes)
#define SM_P     0            // u32 p_w [2][RPC][RSW]        16640
#define SM_PART  16640        // f32 part[2][4][64][PBD]      20480
#define SM_B     37120        // f32 B_sh[NM][NC]             16384
#define SM_LMAX  53504        // f32 lmax[2][RPC][16]          1024
#define SM_C     54528        // f64 c_sh[RPC]                   64
#define SM_MBAR  54592        // u64 mbar[2][4]                  64
#define SM_TOTAL 54784

// Static device scratch
__device__ unsigned short g_sym[NB * TB];            // 2 MB: symbol per (b,t)

// ---- helpers ---------------------------------------------------------------
__device__ __forceinline__ uint32_t bf16x2(float hi, float lo) {
    uint32_t d;
    asm("cvt.rn.bf16x2.f32 %0, %1, %2;" : "=r"(d) : "f"(hi), "f"(lo));
    return d;
}
__device__ __forceinline__ void mma16816(float* d, const uint32_t* a,
                                         uint32_t b0, uint32_t b1) {
    asm("mma.sync.aligned.m16n8k16.row.col.f32.bf16.bf16.f32 "
        "{%0,%1,%2,%3}, {%4,%5,%6,%7}, {%8,%9}, {%0,%1,%2,%3};"
        : "+f"(d[0]), "+f"(d[1]), "+f"(d[2]), "+f"(d[3])
        : "r"(a[0]), "r"(a[1]), "r"(a[2]), "r"(a[3]), "r"(b0), "r"(b1));
}
__device__ __forceinline__ uint32_t mapa_sh(uint32_t addr, uint32_t rank) {
    uint32_t d;
    asm("mapa.shared::cluster.u32 %0, %1, %2;" : "=r"(d) : "r"(addr), "r"(rank));
    return d;
}
__device__ __forceinline__ uint32_t smem_u32(const void* p) {
    uint32_t a;
    asm("{ .reg .u64 t; cvta.to.shared.u64 t, %1; cvt.u32.u64 %0, t; }"
        : "=r"(a) : "l"(p));
    return a;
}
__device__ __forceinline__ void st_async64(uint32_t raddr, unsigned long long v,
                                           uint32_t rmbar) {
    asm volatile("st.async.shared::cluster.mbarrier::complete_tx::bytes.u64 "
                 "[%0], %1, [%2];" :: "r"(raddr), "l"(v), "r"(rmbar) : "memory");
}
__device__ __forceinline__ void st_async32(uint32_t raddr, uint32_t v,
                                           uint32_t rmbar) {
    asm volatile("st.async.shared::cluster.mbarrier::complete_tx::bytes.u32 "
                 "[%0], %1, [%2];" :: "r"(raddr), "r"(v), "r"(rmbar) : "memory");
}
__device__ __forceinline__ void mbar_init(uint32_t addr, uint32_t count) {
    asm volatile("mbarrier.init.shared.b64 [%0], %1;" :: "r"(addr), "r"(count)
                 : "memory");
}
__device__ __forceinline__ void mbar_arm(uint32_t addr, uint32_t tx) {
    asm volatile("mbarrier.arrive.expect_tx.shared.b64 _, [%0], %1;"
                 :: "r"(addr), "r"(tx) : "memory");
}
__device__ __forceinline__ void mbar_wait(uint32_t addr, int parity) {
    asm volatile(
        "{\n\t.reg .pred P;\n"
        "W%=:\n\t"
        "mbarrier.try_wait.parity.acquire.cluster.shared::cta.b64 P, [%0], %1, 0x989680;\n\t"
        "@P bra D%=;\n\t"
        "bra W%=;\n"
        "D%=:\n\t}"
        :: "r"(addr), "r"(parity) : "memory");
}

// ---------------------------------------------------------------------------
// Kernel 0: collapse one-hot x[b,t,:] -> symbol index. 4 threads per position.
// ---------------------------------------------------------------------------
__global__ void extract_sym_kernel(const float* __restrict__ x) {
    int g = blockIdx.x * blockDim.x + threadIdx.x;
    int pos  = g >> 2;
    int part = g & 3;
    const float4* xp = reinterpret_cast<const float4*>(x) + (size_t)pos * 16 + part * 4;
    int found = 0;
#pragma unroll
    for (int i = 0; i < 4; i++) {
        float4 v = xp[i];
        int base = part * 16 + i * 4;
        if (v.x > 0.5f) found = base;
        if (v.y > 0.5f) found = base + 1;
        if (v.z > 0.5f) found = base + 2;
        if (v.w > 0.5f) found = base + 3;
    }
    found = max(found, __shfl_xor_sync(0xFFFFFFFFu, found, 1));
    found = max(found, __shfl_xor_sync(0xFFFFFFFFu, found, 2));
    if (part == 0) g_sym[pos] = (unsigned short)found;
}

// ---------------------------------------------------------------------------
// Kernel 1: persistent clustered forward recurrence, bf16 HMMA + fp32 accum,
//   st.async sync with PER-K-QUARTER mbarriers; 512 threads (4 warps/SMSP).
//   MMA phase:  warp w -> (mt = w&3 m16-tile, kq = w>>2 K-quarter), 8 HMMA.
//               warp waits ONLY its quarter's barrier (src ranks 2kq, 2kq+1).
//   Epilogue:   warp w -> (b = w&7, s-half = w>>3); thread owns one (b, s).
// ---------------------------------------------------------------------------
__global__ void __cluster_dims__(CPC, 1, 1) __launch_bounds__(NT, 1)
hmm_fwd_kernel(const float* __restrict__ A, const float* __restrict__ Bm,
               float* __restrict__ out)
{
    extern __shared__ __align__(16) char smem_raw[];
    uint32_t* p_w  = reinterpret_cast<uint32_t*>(smem_raw + SM_P);   // [2][8][RSW]
    float*    part = reinterpret_cast<float*>(smem_raw + SM_PART);   // [2][4][64][PBD]
    float (*B_sh)[NC] = reinterpret_cast<float(*)[NC]>(smem_raw + SM_B);
    float*    lmax = reinterpret_cast<float*>(smem_raw + SM_LMAX);   // [2][8][16]
    double*   c_sh = reinterpret_cast<double*>(smem_raw + SM_C);

    const int tid  = threadIdx.x;
    const int lane = tid & 31;
    const int warp = tid >> 5;
    const int gid  = lane >> 2;   // mma group id
    const int tig  = lane & 3;    // thread in group
    const int mt   = warp & 3;    // m16 tile
    const int kq   = warp >> 2;   // K-quarter (0..3)
    const int eb   = warp & 7;    // epilogue batch row
    const int esh  = warp >> 3;   // epilogue s-half (0..1)

    uint32_t r_;
    asm("mov.u32 %0, %%cluster_ctarank;" : "=r"(r_));
    const int r    = (int)r_;
    const int cl   = (int)blockIdx.x / CPC;
    const int col0 = r * NC;
    const int myq  = r >> 1;      // quarter our slice belongs to

    const uint32_t smem_base = smem_u32(smem_raw);
    const uint32_t mbar_loc  = smem_base + SM_MBAR;
    uint32_t rank_base[CPC];
#pragma unroll
    for (int rr = 0; rr < CPC; rr++)
        rank_base[rr] = mapa_sh(smem_base, rr);

    if (tid < 8) mbar_init(mbar_loc + tid * 8, 1);

    // ---- A fragments (constant): areg[8 kc][4], this warp's (mt, kq) ----
    uint32_t areg[8][4];
#pragma unroll
    for (int kc = 0; kc < 8; kc++) {
        int m0 = col0 + mt * 16 + gid;
        int k0 = kq * 128 + kc * 16 + tig * 2;
        const float* A0 = A + (size_t)k0 * NS;
        areg[kc][0] = bf16x2(A0[NS + m0],          A0[m0]);
        areg[kc][1] = bf16x2(A0[NS + m0 + 8],      A0[m0 + 8]);
        areg[kc][2] = bf16x2(A0[9 * NS + m0],      A0[8 * NS + m0]);
        areg[kc][3] = bf16x2(A0[9 * NS + m0 + 8],  A0[8 * NS + m0 + 8]);
    }

    // ---- emission slice (fp32) ----
    for (int i = tid; i < NM * NC; i += NT)
        B_sh[i >> 6][i & 63] = Bm[(size_t)(i >> 6) * NS + col0 + (i & 63)];

    if (tid < RPC) c_sh[tid] = 0.0;

    // ---- init buffer 0: p[b][k] = (k==0) ? B[sym0][0] : 0 (bf16 pairs) ----
    for (int i = tid; i < RPC * RSW; i += NT) {
        int b = i / RSW, w = i % RSW;
        uint32_t v = 0;
        if (w == 0) {
            int s0 = g_sym[(size_t)(cl * RPC + b) * TB];
            v = bf16x2(0.0f, Bm[(size_t)s0 * NS]);
        }
        p_w[b * RSW + w] = v;
    }
    if (tid < RPC * 16) {                 // all 16 slots = true max
        int b = tid >> 4;
        int s0 = g_sym[(size_t)(cl * RPC + b) * TB];
        lmax[b * 16 + (tid & 15)] = Bm[(size_t)s0 * NS];
    }
    __syncthreads();
    asm volatile("barrier.cluster.arrive.aligned;" ::: "memory");
    asm volatile("barrier.cluster.wait.aligned;"   ::: "memory");

    int buf = 0, ph0 = 0, ph1 = 0;   // parities for this warp's quarter barrier
    for (int t = 1; t < TB; t++) {
        const int bufn = buf ^ 1;
        // symbol for this warp's epilogue row (independent; overlaps wait)
        const unsigned short symw = __ldg(&g_sym[(size_t)(cl * RPC + eb) * TB + t]);

        // arm the 4 quarter-barriers of the incoming buffer
        if (tid < 4) mbar_arm(mbar_loc + (uint32_t)(bufn * 4 + tid) * 8, TXQ);

        // wait ONLY for this warp's K-quarter of last step's data
        if (t > 1) {
            uint32_t ba = mbar_loc + (uint32_t)(buf * 4 + kq) * 8;
            if (buf == 0) { mbar_wait(ba, ph0); ph0 ^= 1; }
            else          { mbar_wait(ba, ph1); ph1 ^= 1; }
        }

        // -- B fragments for (b = gid, K-quarter kq): ranks 2kq, 2kq+1 only --
        const uint32_t* pb = p_w + buf * (RPC * RSW);
        uint32_t bf0[8], bf1[8];
#pragma unroll
        for (int kc = 0; kc < 8; kc++) {
            int w0 = gid * RSW + kq * 64 + kc * 8 + tig;
            bf0[kc] = pb[w0];
            bf1[kc] = pb[w0 + 4];
        }

        // -- 8 HMMA over 4 interleaved accumulator chains --
        float acc[4][4];
#pragma unroll
        for (int j = 0; j < 4; j++) { acc[j][0] = acc[j][1] = acc[j][2] = acc[j][3] = 0.f; }
#pragma unroll
        for (int kc = 0; kc < 8; kc++)
            mma16816(acc[kc & 3], areg[kc], bf0[kc], bf1[kc]);
        float d0 = (acc[0][0] + acc[1][0]) + (acc[2][0] + acc[3][0]);
        float d1 = (acc[0][1] + acc[1][1]) + (acc[2][1] + acc[3][1]);
        float d2 = (acc[0][2] + acc[1][2]) + (acc[2][2] + acc[3][2]);
        float d3 = (acc[0][3] + acc[1][3]) + (acc[2][3] + acc[3][3]);
        {
            int m  = mt * 16 + gid;
            float* pp = part + ((buf * 4 + kq) * 64 + m) * PBD + 2 * tig;
            *reinterpret_cast<float2*>(pp)           = make_float2(d0, d1);
            *reinterpret_cast<float2*>(pp + 8 * PBD) = make_float2(d2, d3);
        }
        __syncthreads();

        // -- epilogue: thread -> (b = eb, s = esh*32 + lane) --
        const int s = esh * 32 + lane;
        // rv: max over 16 lmax slots for b
        float mx = lmax[(buf * RPC + eb) * 16 + (lane & 15)];
        mx = fmaxf(mx, __shfl_xor_sync(0xFFFFFFFFu, mx, 1));
        mx = fmaxf(mx, __shfl_xor_sync(0xFFFFFFFFu, mx, 2));
        mx = fmaxf(mx, __shfl_xor_sync(0xFFFFFFFFu, mx, 4));
        mx = fmaxf(mx, __shfl_xor_sync(0xFFFFFFFFu, mx, 8));
        const float rv = 1.0f / mx;
        if (esh == 0 && lane == 0) c_sh[eb] += (double)logf(mx);

        const float* pq = part + (buf * 4) * 64 * PBD + s * PBD + eb;
        float u = ((pq[0] + pq[64 * PBD]) + (pq[128 * PBD] + pq[192 * PBD]))
                * rv * B_sh[symw][s];

        // pack 4 states (quad) into one u64 via 2 shuffles
        float up1 = __shfl_xor_sync(0xFFFFFFFFu, u, 1);
        float ulo = (lane & 1) ? up1 : u;
        float uhi = (lane & 1) ? u : up1;
        uint32_t pw  = bf16x2(uhi, ulo);
        uint32_t pw2 = __shfl_xor_sync(0xFFFFFFFFu, pw, 2);
        uint32_t wlo = (lane & 2) ? pw2 : pw;
        uint32_t whi = (lane & 2) ? pw : pw2;
        unsigned long long v2 = ((unsigned long long)whi << 32) | wlo;

        const uint32_t off = SM_P +
            (uint32_t)((bufn * RPC + eb) * RSW + (col0 >> 1) + esh * 16 + ((lane >> 2) << 1)) * 4u;
        const uint32_t rmb_off = SM_MBAR + (uint32_t)(bufn * 4 + myq) * 8u;
        const int r0 = (lane & 3) << 1;        // each quad lane pushes 2 ranks
        st_async64(rank_base[r0]     + off, v2, rank_base[r0]     + rmb_off);
        st_async64(rank_base[r0 + 1] + off, v2, rank_base[r0 + 1] + rmb_off);

        // per-(warp) slice-half max -> all ranks' lmax[bufn][eb][2r + esh]
        float wm = u;
#pragma unroll
        for (int o = 16; o >= 1; o >>= 1)
            wm = fmaxf(wm, __shfl_xor_sync(0xFFFFFFFFu, wm, o));
        if (lane < CPC) {
            uint32_t lo2 = SM_LMAX +
                (uint32_t)((bufn * RPC + eb) * 16 + 2 * r + esh) * 4u;
            st_async32(rank_base[lane] + lo2, __float_as_uint(wm),
                       rank_base[lane] + rmb_off);
        }
        buf = bufn;
    }

    // final wait: this warp's quarter of the last step's data, then join
    {
        uint32_t ba = mbar_loc + (uint32_t)(buf * 4 + kq) * 8;
        if (buf == 0) { mbar_wait(ba, ph0); }
        else          { mbar_wait(ba, ph1); }
    }
    __syncthreads();

    // ---- alpha_T = log(u_T) + C (thread -> (eb, s)) ----
    {
        const int s = esh * 32 + lane;
        uint32_t pw = p_w[(buf * RPC + eb) * RSW + (col0 >> 1) + (s >> 1)];
        float u = (s & 1) ? __uint_as_float(pw & 0xFFFF0000u)
                          : __uint_as_float(pw << 16);
        out[(size_t)(cl * RPC + eb) * NS + col0 + s] =
            (float)((double)logf(u) + c_sh[eb]);
    }
    asm volatile("barrier.cluster.arrive.aligned;" ::: "memory");
    asm volatile("barrier.cluster.wait.aligned;"   ::: "memory");
}

// ---------------------------------------------------------------------------
// Kernel 2: loglik[b] = log(sum_s exp(alpha - m) + S*eps) + m, one warp per row
// ---------------------------------------------------------------------------
__global__ void loglik_kernel(float* __restrict__ out) {
    const int b    = blockIdx.x;
    const int lane = threadIdx.x;
    const float* a = out + (size_t)b * NS;
    float v[16];
    float m = -3.0e38f;
#pragma unroll
    for (int i = 0; i < 16; i++) { v[i] = a[lane + i * 32]; m = fmaxf(m, v[i]); }
#pragma unroll
    for (int o = 16; o >= 1; o >>= 1) m = fmaxf(m, __shfl_xor_sync(0xFFFFFFFFu, m, o));
    float s = 0.f;
#pragma unroll
    for (int i = 0; i < 16; i++) s += expf(v[i] - m);
#pragma unroll
    for (int o = 16; o >= 1; o >>= 1) s += __shfl_xor_sync(0xFFFFFFFFu, s, o);
    if (lane == 0) out[NB * NS + b] = logf(s + 512.0f * 1e-16f) + m;
}

// ---------------------------------------------------------------------------
extern "C" void kernel_launch(void* const* d_in, const int* in_sizes, int n_in,
                              void* d_out, int out_size) {
    const float* x  = nullptr;
    const float* A  = nullptr;
    const float* Bm = nullptr;
    for (int i = 0; i < n_in; i++) {
        if      (in_sizes[i] == NB * TB * NM) x  = (const float*)d_in[i];
        else if (in_sizes[i] == NS * NS)      A  = (const float*)d_in[i];
        else if (in_sizes[i] == NM * NS)      Bm = (const float*)d_in[i];
    }
    if (!x  && n_in > 0) x  = (const float*)d_in[0];
    if (!A  && n_in > 1) A  = (const float*)d_in[1];
    if (!Bm && n_in > 2) Bm = (const float*)d_in[2];

    float* out = (float*)d_out;

    cudaFuncSetAttribute(hmm_fwd_kernel,
                         cudaFuncAttributeMaxDynamicSharedMemorySize, SM_TOTAL);

    extract_sym_kernel<<<(NB * TB * 4) / 256, 256>>>(x);
    hmm_fwd_kernel<<<NCL * CPC, NT, SM_TOTAL>>>(A, Bm, out);
    if (out_size >= NB * NS + NB)
        loglik_kernel<<<NB, 32>>>(out);
}

// round 15
// speedup vs baseline: 1.1429x; 1.1429x over previous
#include <cuda_runtime.h>
#include <math.h>
#include <stdint.h>

// Problem constants
#define TB   8192   // T
#define NB   128    // batch
#define NS   512    // states
#define NM   64     // symbols
#define NCL  16     // clusters (batch groups)
#define RPC  8      // batch rows per cluster
#define CPC  8      // CTAs per cluster (state slices)
#define NC   64     // state columns per CTA
#define RSW  260    // p row stride in 32-bit words (256 data + 4 pad)
#define PSD  76     // part s-dim pad (conflict-free ST + LD)
#define TXB  8192   // expected tx bytes per step: 8 src * 1024 (p only)

// Static device scratch
__device__ unsigned short g_sym[NB * TB];            // 2 MB: symbol per (b,t)

// ---- helpers ---------------------------------------------------------------
__device__ __forceinline__ uint32_t bf16x2(float hi, float lo) {
    uint32_t d;
    asm("cvt.rn.bf16x2.f32 %0, %1, %2;" : "=r"(d) : "f"(hi), "f"(lo));
    return d;
}
__device__ __forceinline__ void mma16816(float* d, const uint32_t* a,
                                         uint32_t b0, uint32_t b1) {
    asm("mma.sync.aligned.m16n8k16.row.col.f32.bf16.bf16.f32 "
        "{%0,%1,%2,%3}, {%4,%5,%6,%7}, {%8,%9}, {%0,%1,%2,%3};"
        : "+f"(d[0]), "+f"(d[1]), "+f"(d[2]), "+f"(d[3])
        : "r"(a[0]), "r"(a[1]), "r"(a[2]), "r"(a[3]), "r"(b0), "r"(b1));
}
__device__ __forceinline__ uint32_t mapa_sh(uint32_t addr, uint32_t rank) {
    uint32_t d;
    asm("mapa.shared::cluster.u32 %0, %1, %2;" : "=r"(d) : "r"(addr), "r"(rank));
    return d;
}
__device__ __forceinline__ uint32_t smem_u32(const void* p) {
    uint32_t a;
    asm("{ .reg .u64 t; cvta.to.shared.u64 t, %1; cvt.u32.u64 %0, t; }"
        : "=r"(a) : "l"(p));
    return a;
}
__device__ __forceinline__ void st_async64(uint32_t raddr, unsigned long long v,
                                           uint32_t rmbar) {
    asm volatile("st.async.shared::cluster.mbarrier::complete_tx::bytes.u64 "
                 "[%0], %1, [%2];" :: "r"(raddr), "l"(v), "r"(rmbar) : "memory");
}
__device__ __forceinline__ void mbar_init(uint32_t addr, uint32_t count) {
    asm volatile("mbarrier.init.shared.b64 [%0], %1;" :: "r"(addr), "r"(count)
                 : "memory");
}
__device__ __forceinline__ void mbar_arm(uint32_t addr, uint32_t tx) {
    asm volatile("mbarrier.arrive.expect_tx.shared.b64 _, [%0], %1;"
                 :: "r"(addr), "r"(tx) : "memory");
}
__device__ __forceinline__ void mbar_wait(uint32_t addr, int parity) {
    asm volatile(
        "{\n\t.reg .pred P;\n"
        "W%=:\n\t"
        "mbarrier.try_wait.parity.acquire.cluster.shared::cta.b64 P, [%0], %1, 0x989680;\n\t"
        "@P bra D%=;\n\t"
        "bra W%=;\n"
        "D%=:\n\t}"
        :: "r"(addr), "r"(parity) : "memory");
}
// per-halfword unsigned max: valid value-max for positive packed bf16
__device__ __forceinline__ uint32_t vmax2(uint32_t a, uint32_t b) {
    return __vmaxu2(a, b);
}

// ---------------------------------------------------------------------------
// Kernel 0: collapse one-hot x[b,t,:] -> symbol index. 4 threads per position.
// ---------------------------------------------------------------------------
__global__ void extract_sym_kernel(const float* __restrict__ x) {
    int g = blockIdx.x * blockDim.x + threadIdx.x;
    int pos  = g >> 2;
    int part = g & 3;
    const float4* xp = reinterpret_cast<const float4*>(x) + (size_t)pos * 16 + part * 4;
    int found = 0;
#pragma unroll
    for (int i = 0; i < 4; i++) {
        float4 v = xp[i];
        int base = part * 16 + i * 4;
        if (v.x > 0.5f) found = base;
        if (v.y > 0.5f) found = base + 1;
        if (v.z > 0.5f) found = base + 2;
        if (v.w > 0.5f) found = base + 3;
    }
    found = max(found, __shfl_xor_sync(0xFFFFFFFFu, found, 1));
    found = max(found, __shfl_xor_sync(0xFFFFFFFFu, found, 2));
    if (part == 0) g_sym[pos] = (unsigned short)found;
}

// ---------------------------------------------------------------------------
// Kernel 1: persistent clustered forward recurrence, bf16 HMMA + fp32 accum,
//   st.async data-driven sync; scale recomputed locally from received p
//   (NO lmax exchange). grid = 128 CTAs, cluster (8,1,1), 256 threads.
//   MMA phase:  warp w -> (mt = w&3 m16-tile, kh = w>>2 K-half), 16 HMMA.
//   Epilogue:   warp w -> batch row b=w; even lanes push ranks 0-3, odd 4-7.
// ---------------------------------------------------------------------------
__global__ void __cluster_dims__(CPC, 1, 1) __launch_bounds__(256, 1)
hmm_fwd_kernel(const float* __restrict__ A, const float* __restrict__ Bm,
               float* __restrict__ out)
{
    __shared__ uint32_t p_w[2][RPC][RSW];          // bf16-pair p, double buffered
    __shared__ float    part[2][2][RPC][PSD];      // [buf][kh][n][m] partials
    __shared__ float    B_sh[NM][NC];              // emission slice
    __shared__ double   c_sh[RPC];                 // running log-scale per row
    __shared__ __align__(8) unsigned long long mbar_sh[2];   // [buf]

    const int tid  = threadIdx.x;
    const int lane = tid & 31;
    const int warp = tid >> 5;
    const int gid  = lane >> 2;   // mma group id
    const int tig  = lane & 3;    // thread in group
    const int mt   = warp & 3;    // m16 tile
    const int kh   = warp >> 2;   // K-half

    uint32_t r_;
    asm("mov.u32 %0, %%cluster_ctarank;" : "=r"(r_));
    const int r    = (int)r_;
    const int cl   = (int)blockIdx.x / CPC;
    const int col0 = r * NC;

    const uint32_t p_base   = smem_u32(&p_w[0][0][0]);
    const uint32_t mbar_loc = smem_u32(&mbar_sh[0]);
    uint32_t p_rem[CPC], mbar_rem[CPC];
#pragma unroll
    for (int rr = 0; rr < CPC; rr++) {
        p_rem[rr]    = mapa_sh(p_base, rr);
        mbar_rem[rr] = mapa_sh(mbar_loc, rr);
    }

    if (tid == 0) { mbar_init(mbar_loc, 1); mbar_init(mbar_loc + 8, 1); }

    // ---- A fragments (constant): areg[16 kc][4], this warp's (mt, kh) ----
    uint32_t areg[16][4];
#pragma unroll
    for (int kc = 0; kc < 16; kc++) {
        int m0 = col0 + mt * 16 + gid;
        int k0 = kh * 256 + kc * 16 + tig * 2;
        const float* A0 = A + (size_t)k0 * NS;
        areg[kc][0] = bf16x2(A0[NS + m0],          A0[m0]);
        areg[kc][1] = bf16x2(A0[NS + m0 + 8],      A0[m0 + 8]);
        areg[kc][2] = bf16x2(A0[9 * NS + m0],      A0[8 * NS + m0]);
        areg[kc][3] = bf16x2(A0[9 * NS + m0 + 8],  A0[8 * NS + m0 + 8]);
    }

    // ---- emission slice (fp32) ----
    for (int i = tid; i < NM * NC; i += 256)
        B_sh[i >> 6][i & 63] = Bm[(size_t)(i >> 6) * NS + col0 + (i & 63)];

    if (tid < RPC) c_sh[tid] = 0.0;

    // ---- init buffer 0: p[b][k] = (k==0) ? B[sym0][0] : 0 (bf16 pairs) ----
    for (int i = tid; i < RPC * RSW; i += 256) {
        int b = i / RSW, w = i % RSW;
        uint32_t v = 0;
        if (w == 0) {
            int s0 = g_sym[(size_t)(cl * RPC + b) * TB];
            v = bf16x2(0.0f, Bm[(size_t)s0 * NS]);
        }
        p_w[0][b][w] = v;
    }
    __syncthreads();
    asm volatile("barrier.cluster.arrive.aligned;" ::: "memory");
    asm volatile("barrier.cluster.wait.aligned;"   ::: "memory");

    int buf = 0, ph0 = 0, ph1 = 0;
    for (int t = 1; t < TB; t++) {
        const int bufn = buf ^ 1;
        // symbol for this warp's epilogue row (independent; overlaps wait)
        const unsigned short symw = __ldg(&g_sym[(size_t)(cl * RPC + warp) * TB + t]);

        // arm receiver mbarrier for incoming bufn data
        if (tid == 0) mbar_arm(mbar_loc + (bufn << 3), TXB);

        // wait for all of last step's data (buffer buf)
        if (t > 1) {
            if (buf == 0) { mbar_wait(mbar_loc,     ph0); ph0 ^= 1; }
            else          { mbar_wait(mbar_loc + 8, ph1); ph1 ^= 1; }
        }

        // -- row max for b = warp, from received p (packed-bf16 SIMD max) --
        // All values positive => unsigned halfword max == value max.
        float rv;
        {
            const uint4* prow = reinterpret_cast<const uint4*>(&p_w[buf][warp][0]);
            uint4 a = prow[lane];
            uint4 b4 = prow[lane + 32];
            uint32_t m = vmax2(vmax2(vmax2(a.x, a.y), vmax2(a.z, a.w)),
                               vmax2(vmax2(b4.x, b4.y), vmax2(b4.z, b4.w)));
#pragma unroll
            for (int o = 16; o >= 1; o >>= 1)
                m = vmax2(m, __shfl_xor_sync(0xFFFFFFFFu, m, o));
            float mhi = __uint_as_float(m & 0xFFFF0000u);
            float mlo = __uint_as_float(m << 16);
            float mx  = fmaxf(mhi, mlo);
            rv = 1.0f / mx;
            if (lane == 0) c_sh[warp] += (double)logf(mx);
        }

        // -- B fragments for (b = gid, K-half kh) --
        const uint32_t* pb = &p_w[buf][0][0];
        uint32_t bf0[16], bf1[16];
#pragma unroll
        for (int kc = 0; kc < 16; kc++) {
            int w0 = gid * RSW + kh * 128 + kc * 8 + tig;
            bf0[kc] = pb[w0];
            bf1[kc] = pb[w0 + 4];
        }

        // -- 16 HMMA over 8 interleaved accumulator chains --
        float acc[8][4];
#pragma unroll
        for (int j = 0; j < 8; j++) { acc[j][0] = acc[j][1] = acc[j][2] = acc[j][3] = 0.f; }
#pragma unroll
        for (int kc = 0; kc < 16; kc++)
            mma16816(acc[kc & 7], areg[kc], bf0[kc], bf1[kc]);
#pragma unroll
        for (int cjs = 0; cjs < 4; cjs++) {
            float d = ((acc[0][cjs] + acc[1][cjs]) + (acc[2][cjs] + acc[3][cjs]))
                    + ((acc[4][cjs] + acc[5][cjs]) + (acc[6][cjs] + acc[7][cjs]));
            int row = 2 * tig + (cjs & 1);
            int m   = mt * 16 + gid + (cjs >> 1) * 8;
            part[buf][kh][row][m] = d;
        }
        __syncthreads();

        // -- epilogue: warp = batch row b=warp, lane = state pair --
        const int s0 = lane * 2;
        float2 q0 = *reinterpret_cast<const float2*>(&part[buf][0][warp][s0]);
        float2 q1 = *reinterpret_cast<const float2*>(&part[buf][1][warp][s0]);
        float2 be = *reinterpret_cast<const float2*>(&B_sh[symw][s0]);
        float u0 = (q0.x + q1.x) * rv * be.x;
        float u1 = (q0.y + q1.y) * rv * be.y;
        uint32_t pw    = bf16x2(u1, u0);
        uint32_t other = __shfl_xor_sync(0xFFFFFFFFu, pw, 1);
        uint32_t lo = (lane & 1) ? other : pw;
        uint32_t hi = (lane & 1) ? pw : other;
        unsigned long long v2 = ((unsigned long long)hi << 32) | lo;
        uint32_t off = (uint32_t)((bufn * RPC + warp) * RSW + (col0 >> 1) + (lane & ~1)) * 4u;
        const uint32_t rmb_off = (uint32_t)(bufn << 3);
        const int rb = (lane & 1) * 4;    // even lanes -> ranks 0-3, odd -> 4-7
#pragma unroll
        for (int j = 0; j < 4; j++)
            st_async64(p_rem[rb + j] + off, v2, mbar_rem[rb + j] + rmb_off);

        buf = bufn;
    }

    // final wait: last step's data
    if (buf == 0) { mbar_wait(mbar_loc,     ph0); }
    else          { mbar_wait(mbar_loc + 8, ph1); }
    __syncthreads();

    // ---- alpha_T = log(u_T) + C ----
    {
        const int b  = warp;
        const int s0 = lane * 2;
        uint32_t pw = p_w[buf][b][(col0 >> 1) + lane];
        float u0 = __uint_as_float(pw << 16);
        float u1 = __uint_as_float(pw & 0xFFFF0000u);
        double cc = c_sh[b];
        out[(size_t)(cl * RPC + b) * NS + col0 + s0]     = (float)((double)logf(u0) + cc);
        out[(size_t)(cl * RPC + b) * NS + col0 + s0 + 1] = (float)((double)logf(u1) + cc);
    }
    asm volatile("barrier.cluster.arrive.aligned;" ::: "memory");
    asm volatile("barrier.cluster.wait.aligned;"   ::: "memory");
}

// ---------------------------------------------------------------------------
// Kernel 2: loglik[b] = log(sum_s exp(alpha - m) + S*eps) + m, one warp per row
// ---------------------------------------------------------------------------
__global__ void loglik_kernel(float* __restrict__ out) {
    const int b    = blockIdx.x;
    const int lane = threadIdx.x;
    const float* a = out + (size_t)b * NS;
    float v[16];
    float m = -3.0e38f;
#pragma unroll
    for (int i = 0; i < 16; i++) { v[i] = a[lane + i * 32]; m = fmaxf(m, v[i]); }
#pragma unroll
    for (int o = 16; o >= 1; o >>= 1) m = fmaxf(m, __shfl_xor_sync(0xFFFFFFFFu, m, o));
    float s = 0.f;
#pragma unroll
    for (int i = 0; i < 16; i++) s += expf(v[i] - m);
#pragma unroll
    for (int o = 16; o >= 1; o >>= 1) s += __shfl_xor_sync(0xFFFFFFFFu, s, o);
    if (lane == 0) out[NB * NS + b] = logf(s + 512.0f * 1e-16f) + m;
}

// ---------------------------------------------------------------------------
extern "C" void kernel_launch(void* const* d_in, const int* in_sizes, int n_in,
                              void* d_out, int out_size) {
    const float* x  = nullptr;
    const float* A  = nullptr;
    const float* Bm = nullptr;
    for (int i = 0; i < n_in; i++) {
        if      (in_sizes[i] == NB * TB * NM) x  = (const float*)d_in[i];
        else if (in_sizes[i] == NS * NS)      A  = (const float*)d_in[i];
        else if (in_sizes[i] == NM * NS)      Bm = (const float*)d_in[i];
    }
    if (!x  && n_in > 0) x  = (const float*)d_in[0];
    if (!A  && n_in > 1) A  = (const float*)d_in[1];
    if (!Bm && n_in > 2) Bm = (const float*)d_in[2];

    float* out = (float*)d_out;

    extract_sym_kernel<<<(NB * TB * 4) / 256, 256>>>(x);
    hmm_fwd_kernel<<<NCL * CPC, 256>>>(A, Bm, out);
    if (out_size >= NB * NS + NB)
        loglik_kernel<<<NB, 32>>>(out);
}